// round 2
// baseline (speedup 1.0000x reference)
#include <cuda_runtime.h>

// Problem constants (fixed by the reference: B=2048, S=128, N=B*S).
#define B_ROWS 2048
#define S_ITEMS 128

// Scratch for per-row results (no device allocation allowed).
__device__ float g_rowvals[B_ROWS];

// One warp per row. Each lane handles 4 consecutive items of the row.
//
// Analytic simplification of the reference (valid because y is one-hot per
// assortment row, which setup_inputs guarantees):
//   result = (1/B) * sum_b [ s_b + log(S - rank_b) ]
// where
//   chosen_b = xa at the one-hot position (== sum(xa*ya) bitwise),
//   s_b      = sum_k relu(xa[b,k] - chosen_b),
//   rank_b   = stable ascending-sort rank of chosen within the row
//            = #{k: xa<chosen} + #{k<pos: xa==chosen}.
__global__ void __launch_bounds__(256) exp_loss_rows(
    const float* __restrict__ x,
    const float* __restrict__ y,
    const int*   __restrict__ assort)
{
    int warp = (blockIdx.x * blockDim.x + threadIdx.x) >> 5;
    int lane = threadIdx.x & 31;
    if (warp >= B_ROWS) return;

    // Vectorized load of 4 item indices for this lane.
    const int4* arow = reinterpret_cast<const int4*>(assort + warp * S_ITEMS);
    int4 a = arow[lane];
    int idx4[4] = {a.x, a.y, a.z, a.w};

    float xv[4], yv[4];
#pragma unroll
    for (int i = 0; i < 4; i++) {
        xv[i] = __ldg(x + idx4[i]);
        yv[i] = __ldg(y + idx4[i]);
    }

    // chosen = sum(xa * ya); exact since all but one term are +-0.
    float ch = 0.0f;
#pragma unroll
    for (int i = 0; i < 4; i++) ch += xv[i] * yv[i];
#pragma unroll
    for (int o = 16; o; o >>= 1) ch += __shfl_xor_sync(0xffffffffu, ch, o);

    // position of the chosen item within the row (for stable-sort ties).
    int pos = -1;
#pragma unroll
    for (int i = 0; i < 4; i++)
        if (yv[i] != 0.0f) pos = lane * 4 + i;
#pragma unroll
    for (int o = 16; o; o >>= 1) pos = max(pos, __shfl_xor_sync(0xffffffffu, pos, o));

    // s = sum relu(xa - chosen);  rank = stable ascending-sort rank of chosen.
    float s = 0.0f;
    int rank = 0;
#pragma unroll
    for (int i = 0; i < 4; i++) {
        float d = xv[i] - ch;
        s += fmaxf(d, 0.0f);
        int gi = lane * 4 + i;
        rank += (xv[i] < ch) || (xv[i] == ch && gi < pos);
    }
#pragma unroll
    for (int o = 16; o; o >>= 1) {
        s    += __shfl_xor_sync(0xffffffffu, s, o);
        rank += __shfl_xor_sync(0xffffffffu, rank, o);
    }

    if (lane == 0)
        g_rowvals[warp] = s + logf((float)(S_ITEMS - rank));
}

// Deterministic single-block reduction of the 2048 per-row values.
__global__ void __launch_bounds__(256) exp_loss_reduce(float* __restrict__ out)
{
    __shared__ double sm[256];
    double acc = 0.0;
    for (int i = threadIdx.x; i < B_ROWS; i += 256)
        acc += (double)g_rowvals[i];
    sm[threadIdx.x] = acc;
    __syncthreads();
#pragma unroll
    for (int stride = 128; stride; stride >>= 1) {
        if (threadIdx.x < stride) sm[threadIdx.x] += sm[threadIdx.x + stride];
        __syncthreads();
    }
    if (threadIdx.x == 0)
        out[0] = (float)(sm[0] / (double)B_ROWS);
}

extern "C" void kernel_launch(void* const* d_in, const int* in_sizes, int n_in,
                              void* d_out, int out_size)
{
    const float* x      = (const float*)d_in[0];
    const float* y      = (const float*)d_in[1];
    const int*   assort = (const int*)d_in[2];

    // 2048 rows, 1 warp/row, 8 warps per 256-thread block -> 256 blocks.
    exp_loss_rows<<<B_ROWS / 8, 256>>>(x, y, assort);
    exp_loss_reduce<<<1, 256>>>((float*)d_out);
}

// round 3
// speedup vs baseline: 1.1866x; 1.1866x over previous
#include <cuda_runtime.h>

// Problem constants (fixed by the reference: B=2048, S=128, N=B*S).
#define B_ROWS   2048
#define S_ITEMS  128
#define WARPS_PB 8                      // warps per block
#define NBLOCKS  (B_ROWS / WARPS_PB)    // 256 blocks

// Scratch (no device allocation allowed -> __device__ globals).
__device__ float        g_partial[NBLOCKS];
__device__ unsigned int g_ticket;       // zero-initialized; last block resets to 0

// Analytic simplification of the reference (valid because y is one-hot per
// assortment row, which setup_inputs guarantees):
//   result = (1/B) * sum_b [ s_b + log(S - rank_b) ]
// where
//   chosen_b = xa at the one-hot position (== sum(xa*ya) bitwise),
//   s_b      = sum_k relu(xa[b,k] - chosen_b),
//   rank_b   = stable ascending-sort rank of chosen within the row
//            = #{k: xa<chosen} + #{k<pos: xa==chosen}.
//
// Single fused kernel: one warp per row (lane handles 4 items), block reduces
// its 8 row values to one partial; the last-arriving block deterministically
// reduces the 256 partials and writes the scalar output.
__global__ void __launch_bounds__(256) exp_loss_fused(
    const float* __restrict__ x,
    const float* __restrict__ y,
    const int*   __restrict__ assort,
    float*       __restrict__ out)
{
    const int lane   = threadIdx.x & 31;
    const int warpid = threadIdx.x >> 5;                 // 0..7
    const int row    = blockIdx.x * WARPS_PB + warpid;   // 0..2047

    // ---- per-row computation (one warp per row) ----
    const int4* arow = reinterpret_cast<const int4*>(assort + row * S_ITEMS);
    int4 a = arow[lane];
    int idx4[4] = {a.x, a.y, a.z, a.w};

    float xv[4], yv[4];
#pragma unroll
    for (int i = 0; i < 4; i++) {
        xv[i] = __ldg(x + idx4[i]);
        yv[i] = __ldg(y + idx4[i]);
    }

    // chosen = sum(xa * ya); exact since all but one term are +-0.
    float ch = 0.0f;
#pragma unroll
    for (int i = 0; i < 4; i++) ch += xv[i] * yv[i];
#pragma unroll
    for (int o = 16; o; o >>= 1) ch += __shfl_xor_sync(0xffffffffu, ch, o);

    // position of the chosen item within the row (stable-sort tie break).
    int pos = -1;
#pragma unroll
    for (int i = 0; i < 4; i++)
        if (yv[i] != 0.0f) pos = lane * 4 + i;
#pragma unroll
    for (int o = 16; o; o >>= 1) pos = max(pos, __shfl_xor_sync(0xffffffffu, pos, o));

    // s = sum relu(xa - chosen);  rank = stable ascending rank of chosen.
    float s = 0.0f;
    int rank = 0;
#pragma unroll
    for (int i = 0; i < 4; i++) {
        float d = xv[i] - ch;
        s += fmaxf(d, 0.0f);
        int gi = lane * 4 + i;
        rank += (xv[i] < ch) || (xv[i] == ch && gi < pos);
    }
#pragma unroll
    for (int o = 16; o; o >>= 1) {
        s    += __shfl_xor_sync(0xffffffffu, s, o);
        rank += __shfl_xor_sync(0xffffffffu, rank, o);
    }

    // ---- block partial: reduce 8 warp values deterministically ----
    __shared__ float  warpval[WARPS_PB];
    __shared__ int    is_last;
    if (lane == 0)
        warpval[warpid] = s + logf((float)(S_ITEMS - rank));
    __syncthreads();

    if (threadIdx.x == 0) {
        double acc = 0.0;
#pragma unroll
        for (int i = 0; i < WARPS_PB; i++) acc += (double)warpval[i];
        g_partial[blockIdx.x] = (float)acc;
        __threadfence();
        unsigned int t = atomicAdd(&g_ticket, 1u);
        is_last = (t == (unsigned int)(gridDim.x - 1));
    }
    __syncthreads();

    // ---- last block: deterministic tree reduction of the 256 partials ----
    if (is_last) {
        __shared__ double sm[NBLOCKS];
        sm[threadIdx.x] = (double)g_partial[threadIdx.x];   // 256 == NBLOCKS
        __syncthreads();
#pragma unroll
        for (int stride = NBLOCKS / 2; stride; stride >>= 1) {
            if (threadIdx.x < stride) sm[threadIdx.x] += sm[threadIdx.x + stride];
            __syncthreads();
        }
        if (threadIdx.x == 0) {
            out[0] = (float)(sm[0] / (double)B_ROWS);
            g_ticket = 0;   // reset for next graph replay
        }
    }
}

extern "C" void kernel_launch(void* const* d_in, const int* in_sizes, int n_in,
                              void* d_out, int out_size)
{
    const float* x      = (const float*)d_in[0];
    const float* y      = (const float*)d_in[1];
    const int*   assort = (const int*)d_in[2];

    exp_loss_fused<<<NBLOCKS, 256>>>(x, y, assort, (float*)d_out);
}

// round 4
// speedup vs baseline: 1.2186x; 1.0269x over previous
#include <cuda_runtime.h>

// Problem constants (fixed by the reference: B=2048, S=128, N=B*S).
#define B_ROWS   2048
#define S_ITEMS  128
#define WARPS_PB 8                      // warps per block
#define NBLOCKS  (B_ROWS / WARPS_PB)    // 256 blocks
#define GROUPS   16                     // two-level ticket: 16 groups of 16 blocks
#define GSIZE    (NBLOCKS / GROUPS)     // 16

// Scratch (no device allocation allowed -> __device__ globals, zero-initialized).
__device__ float        g_partial[NBLOCKS];
__device__ unsigned int g_cnt1[GROUPS * 32];   // 128B stride -> distinct L2 slices
__device__ unsigned int g_cnt2;

// Analytic simplification of the reference (valid because y is one-hot per
// assortment row, which setup_inputs guarantees):
//   result = (1/B) * sum_b [ s_b + log(S - rank_b) ]
// where
//   chosen_b = xa at the one-hot position (== sum(xa*ya) bitwise),
//   s_b      = sum_k relu(xa[b,k] - chosen_b),
//   rank_b   = stable ascending-sort rank of chosen within the row
//            = #{k: xa<chosen} + #{k<pos: xa==chosen}.
__global__ void __launch_bounds__(256) exp_loss_fused(
    const float* __restrict__ x,
    const float* __restrict__ y,
    const int*   __restrict__ assort,
    float*       __restrict__ out)
{
    const unsigned FULL = 0xffffffffu;
    const int lane   = threadIdx.x & 31;
    const int warpid = threadIdx.x >> 5;                 // 0..7
    const int row    = blockIdx.x * WARPS_PB + warpid;   // 0..2047

    // ---- per-row computation (one warp per row, 4 items per lane) ----
    const int4* arow = reinterpret_cast<const int4*>(assort + row * S_ITEMS);
    int4 a = arow[lane];
    int idx4[4] = {a.x, a.y, a.z, a.w};

    float xv[4], yv[4];
#pragma unroll
    for (int i = 0; i < 4; i++) {
        xv[i] = __ldg(x + idx4[i]);
        yv[i] = __ldg(y + idx4[i]);
    }

    // Locate the one-hot item: local chosen value + local position, then a
    // single ballot + broadcast instead of full shfl reduction chains.
    float lch = 0.0f;
    int   lpos = -1;
#pragma unroll
    for (int i = 0; i < 4; i++) {
        lch += xv[i] * yv[i];              // exact: other terms are +-0
        if (yv[i] != 0.0f) lpos = lane * 4 + i;
    }
    unsigned bal = __ballot_sync(FULL, lpos >= 0);
    int src = __ffs(bal) - 1;              // exactly one lane holds the item
    float ch  = __shfl_sync(FULL, lch,  src);
    int   pos = __shfl_sync(FULL, lpos, src);

    // s = sum relu(xa - chosen);  rank = stable ascending rank of chosen.
    float s = 0.0f;
    int rank = 0;
#pragma unroll
    for (int i = 0; i < 4; i++) {
        s += fmaxf(xv[i] - ch, 0.0f);
        int gi = lane * 4 + i;
        rank += (xv[i] < ch) || (xv[i] == ch && gi < pos);
    }
    rank = __reduce_add_sync(FULL, rank);  // REDUX.SUM, single instruction
#pragma unroll
    for (int o = 16; o; o >>= 1)
        s += __shfl_xor_sync(FULL, s, o);

    // ---- block partial: reduce 8 warp values deterministically ----
    __shared__ float warpval[WARPS_PB];
    __shared__ int   is_last;
    if (lane == 0)
        warpval[warpid] = s + logf((float)(S_ITEMS - rank));
    __syncthreads();

    if (threadIdx.x == 0) {
        double acc = 0.0;
#pragma unroll
        for (int i = 0; i < WARPS_PB; i++) acc += (double)warpval[i];
        g_partial[blockIdx.x] = (float)acc;
        __threadfence();
        // Two-level ticket: 16 spread counters (128B apart) absorb the
        // per-address L2 atomic serialization; one small super-counter on top.
        int grp = blockIdx.x & (GROUPS - 1);
        unsigned t1 = atomicAdd(&g_cnt1[grp * 32], 1u);
        int last = 0;
        if (t1 == GSIZE - 1) {
            unsigned t2 = atomicAdd(&g_cnt2, 1u);
            last = (t2 == GROUPS - 1);
        }
        is_last = last;
    }
    __syncthreads();

    // ---- last block: deterministic tree reduction of the 256 partials ----
    if (is_last) {
        __shared__ double sm[NBLOCKS];
        sm[threadIdx.x] = (double)g_partial[threadIdx.x];   // 256 == NBLOCKS
        __syncthreads();
#pragma unroll
        for (int stride = NBLOCKS / 2; stride; stride >>= 1) {
            if (threadIdx.x < stride) sm[threadIdx.x] += sm[threadIdx.x + stride];
            __syncthreads();
        }
        // Reset tickets for the next graph replay (all atomics already done:
        // g_cnt2 reached GROUPS implies every g_cnt1 group is full).
        if (threadIdx.x < GROUPS) g_cnt1[threadIdx.x * 32] = 0u;
        if (threadIdx.x == 0) {
            g_cnt2 = 0u;
            out[0] = (float)(sm[0] / (double)B_ROWS);
        }
    }
}

extern "C" void kernel_launch(void* const* d_in, const int* in_sizes, int n_in,
                              void* d_out, int out_size)
{
    const float* x      = (const float*)d_in[0];
    const float* y      = (const float*)d_in[1];
    const int*   assort = (const int*)d_in[2];

    exp_loss_fused<<<NBLOCKS, 256>>>(x, y, assort, (float*)d_out);
}